// round 1
// baseline (speedup 1.0000x reference)
#include <cuda_runtime.h>
#include <cstdint>
#include <math_constants.h>

#define BATCH 16
#define CDIM  2048
#define TDIM  8192
#define KEEP  64

// Scratch (allocation-free rule: __device__ globals)
__device__ float g_attn[BATCH * TDIM];
__device__ int   g_idx [BATCH * KEEP];
__device__ float g_val [BATCH * KEEP];

// ---------------- Kernel 1: attn[b,t] = sum_c x[b,c,t]*w[c] + bias ----------------
// Block: 512 threads = 128 t-lanes (float4 -> 4 t each) x 4 c-partitions.
// Grid: (TDIM/512, BATCH) = (16, 16) = 256 blocks.
constexpr int LANES  = 128;
constexpr int CSPLIT = 4;
constexpr int TCHUNK = LANES * 4;   // 512 t per block
constexpr int CSEG   = CDIM / CSPLIT;

__global__ __launch_bounds__(LANES * CSPLIT, 2)
void attn_kernel(const float* __restrict__ x,
                 const float* __restrict__ w,
                 const float* __restrict__ bias)
{
    __shared__ float  ws[CDIM];
    __shared__ float4 red[(CSPLIT - 1) * LANES];

    const int tid = threadIdx.x;
    for (int i = tid; i < CDIM; i += LANES * CSPLIT) ws[i] = w[i];
    __syncthreads();

    const int lane  = tid & (LANES - 1);
    const int cpart = tid >> 7;          // tid / 128
    const int b     = blockIdx.y;
    const int t4    = blockIdx.x * LANES + lane;   // float4 index along t

    const float4* __restrict__ x4 =
        reinterpret_cast<const float4*>(x) + (size_t)b * CDIM * (TDIM / 4);

    float4 acc = make_float4(0.f, 0.f, 0.f, 0.f);
    const int cbeg = cpart * CSEG;

    #pragma unroll 8
    for (int c = cbeg; c < cbeg + CSEG; ++c) {
        const float  wv = ws[c];
        const float4 xv = x4[(size_t)c * (TDIM / 4) + t4];
        acc.x = fmaf(xv.x, wv, acc.x);
        acc.y = fmaf(xv.y, wv, acc.y);
        acc.z = fmaf(xv.z, wv, acc.z);
        acc.w = fmaf(xv.w, wv, acc.w);
    }

    if (cpart > 0) red[(cpart - 1) * LANES + lane] = acc;
    __syncthreads();

    if (cpart == 0) {
        #pragma unroll
        for (int p = 0; p < CSPLIT - 1; ++p) {
            const float4 r = red[p * LANES + lane];
            acc.x += r.x; acc.y += r.y; acc.z += r.z; acc.w += r.w;
        }
        const float bb = bias[0];
        float4 o = make_float4(acc.x + bb, acc.y + bb, acc.z + bb, acc.w + bb);
        reinterpret_cast<float4*>(g_attn + (size_t)b * TDIM)[t4] = o;
    }
}

// ---------------- Kernel 2: top-64 per batch (values descending, ties -> lower index) --------
__global__ __launch_bounds__(256)
void topk_kernel()
{
    __shared__ float sv[TDIM];       // 32 KB working copy
    __shared__ float lmax[256];
    __shared__ int   lidx[256];
    __shared__ float wmax[8];
    __shared__ int   widx[8];
    __shared__ int   s_sel;

    const int tid = threadIdx.x;
    const int b   = blockIdx.x;
    const float* __restrict__ a = g_attn + (size_t)b * TDIM;

    for (int i = tid; i < TDIM; i += 256) sv[i] = a[i];
    __syncthreads();

    // Each thread owns a contiguous segment of 32 values.
    const int base = tid * 32;
    {
        float bm = -CUDART_INF_F; int bi = 0;
        #pragma unroll 8
        for (int i = 0; i < 32; ++i) {
            const float v = sv[base + i];
            if (v > bm) { bm = v; bi = base + i; }   // strict > keeps lowest index
        }
        lmax[tid] = bm; lidx[tid] = bi;
    }
    __syncthreads();

    for (int k = 0; k < KEEP; ++k) {
        float v  = lmax[tid];
        int   id = lidx[tid];
        #pragma unroll
        for (int off = 16; off; off >>= 1) {
            const float ov = __shfl_down_sync(0xffffffffu, v, off);
            const int   oi = __shfl_down_sync(0xffffffffu, id, off);
            if (ov > v || (ov == v && oi < id)) { v = ov; id = oi; }
        }
        if ((tid & 31) == 0) { wmax[tid >> 5] = v; widx[tid >> 5] = id; }
        __syncthreads();

        if (tid == 0) {
            float bv = wmax[0]; int bI = widx[0];
            #pragma unroll
            for (int wgi = 1; wgi < 8; ++wgi) {
                const float ov = wmax[wgi]; const int oi = widx[wgi];
                if (ov > bv || (ov == bv && oi < bI)) { bv = ov; bI = oi; }
            }
            g_idx[b * KEEP + k] = bI;
            g_val[b * KEEP + k] = bv;
            s_sel = bI;
            sv[bI] = -CUDART_INF_F;
        }
        __syncthreads();

        const int sel = s_sel;
        if ((sel >> 5) == tid) {   // only the owning segment recomputes
            float bm = -CUDART_INF_F; int bi = 0;
            #pragma unroll 8
            for (int i = 0; i < 32; ++i) {
                const float vv = sv[base + i];
                if (vv > bm) { bm = vv; bi = base + i; }
            }
            lmax[tid] = bm; lidx[tid] = bi;
        }
        __syncthreads();
    }
}

// ---------------- Kernel 3: gather latents[b,k,c] = x[b,c,idx]*scale ----------------
__global__ __launch_bounds__(256)
void gather_kernel(const float* __restrict__ x, float* __restrict__ out)
{
    const int b = blockIdx.y;
    const int k = blockIdx.x;
    const int t = g_idx[b * KEEP + k];
    const float v = g_val[b * KEEP + k];
    const float scale = v + (1.0f - v);   // match reference rounding exactly

    const float* __restrict__ xp = x + (size_t)b * CDIM * TDIM + t;
    float* __restrict__ op = out + ((size_t)b * KEEP + k) * CDIM;

    #pragma unroll 4
    for (int c = threadIdx.x; c < CDIM; c += 256)
        op[c] = xp[(size_t)c * TDIM] * scale;
}

// ---------------- Kernel 4: indices as float32 appended after latents ----------------
__global__ void write_idx_kernel(float* __restrict__ out)
{
    const int i = blockIdx.x * blockDim.x + threadIdx.x;
    if (i < BATCH * KEEP) out[i] = (float)g_idx[i];
}

extern "C" void kernel_launch(void* const* d_in, const int* in_sizes, int n_in,
                              void* d_out, int out_size)
{
    const float* x    = (const float*)d_in[0];
    const float* w    = (const float*)d_in[1];
    const float* bias = (const float*)d_in[2];
    float* out = (float*)d_out;

    dim3 g1(TDIM / TCHUNK, BATCH);                 // (16, 16)
    attn_kernel<<<g1, LANES * CSPLIT>>>(x, w, bias);

    topk_kernel<<<BATCH, 256>>>();

    dim3 g3(KEEP, BATCH);                          // (64, 16)
    gather_kernel<<<g3, 256>>>(x, out);

    const int lat_elems = BATCH * KEEP * CDIM;     // 2,097,152
    if (out_size >= lat_elems + BATCH * KEEP) {
        write_idx_kernel<<<(BATCH * KEEP + 255) / 256, 256>>>(out + lat_elems);
    }
}

// round 2
// speedup vs baseline: 1.0844x; 1.0844x over previous
#include <cuda_runtime.h>
#include <cstdint>
#include <math_constants.h>

#define BATCH 16
#define CDIM  2048
#define TDIM  8192
#define KEEP  64

// Scratch (allocation-free rule: __device__ globals)
__device__ float    g_attn[BATCH * TDIM];
__device__ int      g_idx [BATCH * KEEP];
__device__ float    g_val [BATCH * KEEP];
__device__ unsigned g_ctr [BATCH];          // zero-init; reset by topk block each run

// ---------------- Fused kernel: attn matvec + per-batch top-64 ----------------
// Block: 512 threads = 128 t-lanes (float4 -> 4 t each) x 4 c-partitions.
// Grid: (TDIM/512, BATCH) = (16, 16) = 256 blocks.
// The 16th block to finish a batch runs top-64 for that batch (overlaps with
// the attn tail of other batches).
constexpr int LANES   = 128;
constexpr int CSPLIT  = 4;
constexpr int NTHR    = LANES * CSPLIT;     // 512
constexpr int TCHUNK  = LANES * 4;          // 512 t per block
constexpr int CSEG    = CDIM / CSPLIT;
constexpr int BLK_PER_B = TDIM / TCHUNK;    // 16
constexpr int SEG     = TDIM / NTHR;        // 16 values per thread in topk

__global__ __launch_bounds__(NTHR, 2)
void attn_topk_kernel(const float* __restrict__ x,
                      const float* __restrict__ w,
                      const float* __restrict__ bias)
{
    __shared__ union {
        struct { float ws[CDIM]; float4 red[(CSPLIT - 1) * LANES]; } a; // 9.5 KB
        struct { float sv[TDIM]; } t;                                   // 32 KB
    } sm;
    __shared__ float lmax[NTHR];
    __shared__ int   lidx[NTHR];
    __shared__ float wmax[NTHR / 32];
    __shared__ int   widx[NTHR / 32];
    __shared__ int   s_sel;
    __shared__ int   s_last;

    const int tid = threadIdx.x;
    const int b   = blockIdx.y;

    // ---- phase 1: attn ----
    for (int i = tid; i < CDIM; i += NTHR) sm.a.ws[i] = w[i];
    __syncthreads();

    const int lane  = tid & (LANES - 1);
    const int cpart = tid >> 7;
    const int t4    = blockIdx.x * LANES + lane;     // float4 index along t

    const float4* __restrict__ x4 =
        reinterpret_cast<const float4*>(x) + (size_t)b * CDIM * (TDIM / 4);

    float4 acc = make_float4(0.f, 0.f, 0.f, 0.f);
    const int cbeg = cpart * CSEG;

    #pragma unroll 8
    for (int c = cbeg; c < cbeg + CSEG; ++c) {
        const float  wv = sm.a.ws[c];
        const float4 xv = x4[(size_t)c * (TDIM / 4) + t4];
        acc.x = fmaf(xv.x, wv, acc.x);
        acc.y = fmaf(xv.y, wv, acc.y);
        acc.z = fmaf(xv.z, wv, acc.z);
        acc.w = fmaf(xv.w, wv, acc.w);
    }

    if (cpart > 0) sm.a.red[(cpart - 1) * LANES + lane] = acc;
    __syncthreads();

    if (cpart == 0) {
        #pragma unroll
        for (int p = 0; p < CSPLIT - 1; ++p) {
            const float4 r = sm.a.red[p * LANES + lane];
            acc.x += r.x; acc.y += r.y; acc.z += r.z; acc.w += r.w;
        }
        const float bb = bias[0];
        float4 o = make_float4(acc.x + bb, acc.y + bb, acc.z + bb, acc.w + bb);
        reinterpret_cast<float4*>(g_attn + (size_t)b * TDIM)[t4] = o;
        __threadfence();                       // release attn writes
    }
    __syncthreads();

    if (tid == 0) {
        const unsigned old = atomicAdd(&g_ctr[b], 1u);
        s_last = (old == BLK_PER_B - 1);
    }
    __syncthreads();
    if (!s_last) return;

    // ---- phase 2: top-64 for batch b (only the last-arriving block) ----
    float* __restrict__ sv = sm.t.sv;
    {
        const float* __restrict__ a = g_attn + (size_t)b * TDIM;
        for (int i = tid; i < TDIM; i += NTHR) sv[i] = __ldcg(&a[i]);
    }
    __syncthreads();

    const int base = tid * SEG;
    {
        float bm = -CUDART_INF_F; int bi = 0;
        #pragma unroll
        for (int i = 0; i < SEG; ++i) {
            const float v = sv[base + i];
            if (v > bm) { bm = v; bi = base + i; }   // strict > keeps lowest index
        }
        lmax[tid] = bm; lidx[tid] = bi;
    }
    __syncthreads();

    for (int k = 0; k < KEEP; ++k) {
        float v  = lmax[tid];
        int   id = lidx[tid];
        #pragma unroll
        for (int off = 16; off; off >>= 1) {
            const float ov = __shfl_down_sync(0xffffffffu, v, off);
            const int   oi = __shfl_down_sync(0xffffffffu, id, off);
            if (ov > v || (ov == v && oi < id)) { v = ov; id = oi; }
        }
        if ((tid & 31) == 0) { wmax[tid >> 5] = v; widx[tid >> 5] = id; }
        __syncthreads();

        if (tid == 0) {
            float bv = wmax[0]; int bI = widx[0];
            #pragma unroll
            for (int wgi = 1; wgi < NTHR / 32; ++wgi) {
                const float ov = wmax[wgi]; const int oi = widx[wgi];
                if (ov > bv || (ov == bv && oi < bI)) { bv = ov; bI = oi; }
            }
            g_idx[b * KEEP + k] = bI;
            g_val[b * KEEP + k] = bv;
            s_sel = bI;
            sv[bI] = -CUDART_INF_F;
        }
        __syncthreads();

        const int sel = s_sel;
        if ((sel / SEG) == tid) {               // only owning segment recomputes
            float bm = -CUDART_INF_F; int bi = 0;
            #pragma unroll
            for (int i = 0; i < SEG; ++i) {
                const float vv = sv[base + i];
                if (vv > bm) { bm = vv; bi = base + i; }
            }
            lmax[tid] = bm; lidx[tid] = bi;
        }
        __syncthreads();
    }

    if (tid == 0) g_ctr[b] = 0;                 // reset for next graph replay
}

// ---------------- Kernel 2: gather latents + write indices ----------------
__global__ __launch_bounds__(256)
void gather_kernel(const float* __restrict__ x, float* __restrict__ out,
                   int write_indices)
{
    const int b = blockIdx.y;
    const int k = blockIdx.x;
    const int t = g_idx[b * KEEP + k];
    const float v = g_val[b * KEEP + k];
    const float scale = v + (1.0f - v);          // match reference rounding exactly

    const float* __restrict__ xp = x + (size_t)b * CDIM * TDIM + t;
    float* __restrict__ op = out + ((size_t)b * KEEP + k) * CDIM;

    #pragma unroll 4
    for (int c = threadIdx.x; c < CDIM; c += 256)
        op[c] = xp[(size_t)c * TDIM] * scale;

    if (write_indices && threadIdx.x == 0)
        out[(size_t)BATCH * KEEP * CDIM + b * KEEP + k] = (float)t;
}

extern "C" void kernel_launch(void* const* d_in, const int* in_sizes, int n_in,
                              void* d_out, int out_size)
{
    const float* x    = (const float*)d_in[0];
    const float* w    = (const float*)d_in[1];
    const float* bias = (const float*)d_in[2];
    float* out = (float*)d_out;

    dim3 g1(BLK_PER_B, BATCH);                   // (16, 16)
    attn_topk_kernel<<<g1, NTHR>>>(x, w, bias);

    const int lat_elems = BATCH * KEEP * CDIM;   // 2,097,152
    const int widx = (out_size >= lat_elems + BATCH * KEEP) ? 1 : 0;
    dim3 g2(KEEP, BATCH);                        // (64, 16)
    gather_kernel<<<g2, 256>>>(x, out, widx);
}